// round 4
// baseline (speedup 1.0000x reference)
#include <cuda_runtime.h>
#include <math.h>

#define MROWS 1024
#define KDIM  512
#define CCLS  85742
#define S_SCALE 64.0f
#define MARGIN  0.5f
#define EPS_CL  1e-7f

#define BM 128
#define BN 128
#define BK 16
#define LDSA 20   // smem row stride (floats): bank-conflict-free for frag LDS, 16B-aligned

__device__ float g_xn[MROWS * KDIM];
__device__ float g_rowsum[MROWS];

// ---------------------------------------------------------------------------
// Kernel 1: L2-normalize rows of x into g_xn, zero g_rowsum (re-done on every
// graph replay, so rowsum accumulation stays deterministic).
// ---------------------------------------------------------------------------
__global__ void normalize_kernel(const float* __restrict__ x) {
    int row = blockIdx.x;
    int t   = threadIdx.x;                 // 128 threads, 4 floats each
    float4 v = ((const float4*)(x + (size_t)row * KDIM))[t];
    float s = v.x * v.x + v.y * v.y + v.z * v.z + v.w * v.w;
    #pragma unroll
    for (int o = 16; o > 0; o >>= 1) s += __shfl_xor_sync(0xffffffffu, s, o);
    __shared__ float ws[4];
    int lane = t & 31, wid = t >> 5;
    if (lane == 0) ws[wid] = s;
    __syncthreads();
    float tot = ws[0] + ws[1] + ws[2] + ws[3];
    float inv = 1.0f / fmaxf(sqrtf(tot), 1e-12f);
    float4 o4 = make_float4(v.x * inv, v.y * inv, v.z * inv, v.w * inv);
    ((float4*)(g_xn + (size_t)row * KDIM))[t] = o4;
    if (t == 0) g_rowsum[row] = 0.0f;
}

// ---------------------------------------------------------------------------
// TF32 helpers
// ---------------------------------------------------------------------------
__device__ __forceinline__ unsigned f2tf32(float f) {
    unsigned u;
    asm("cvt.rna.tf32.f32 %0, %1;" : "=r"(u) : "f"(f));
    return u;
}

__device__ __forceinline__ void mma_tf32(float* d, const unsigned* a, const unsigned* b) {
    asm volatile(
        "mma.sync.aligned.m16n8k8.row.col.f32.tf32.tf32.f32 "
        "{%0,%1,%2,%3}, {%4,%5,%6,%7}, {%8,%9}, {%0,%1,%2,%3};"
        : "+f"(d[0]), "+f"(d[1]), "+f"(d[2]), "+f"(d[3])
        : "r"(a[0]), "r"(a[1]), "r"(a[2]), "r"(a[3]), "r"(b[0]), "r"(b[1]));
}

// ---------------------------------------------------------------------------
// Kernel 2: wf = xn @ W^T  (TF32 tensor-core GEMM, 128x128x16 tiles, double
// buffered) with fused per-row sum of exp(64*wf) via atomics.
// Both operands are K-contiguous -> row.col mma.
// ---------------------------------------------------------------------------
__global__ __launch_bounds__(256, 2)
void gemm_kernel(const float* __restrict__ W, float* __restrict__ wf) {
    __shared__ float As[2][BM * LDSA];
    __shared__ float Bs[2][BN * LDSA];

    const int tid   = threadIdx.x;
    const int lane  = tid & 31;
    const int warp  = tid >> 5;
    const int warpM = warp & 1;     // 2 warps in M
    const int warpN = warp >> 1;    // 4 warps in N
    const int g     = lane >> 2;    // groupID
    const int t     = lane & 3;     // thread-in-group
    const int rowBase = blockIdx.y * BM;   // sample tile
    const int colBase = blockIdx.x * BN;   // class tile

    float acc[4][4][4];
    #pragma unroll
    for (int mi = 0; mi < 4; ++mi)
        #pragma unroll
        for (int ni = 0; ni < 4; ++ni)
            #pragma unroll
            for (int r = 0; r < 4; ++r) acc[mi][ni][r] = 0.0f;

    // staging mapping: slot s in [0,512): row m = s>>2, k-quad kq = (s&3)*4
    const int m0  = tid >> 2,          kq0 = (tid & 3) * 4;
    const int m1  = (tid + 256) >> 2,  kq1 = ((tid + 256) & 3) * 4;

    float4 aR0, aR1, bR0, bR1;

    auto stage4 = [](float* dst, float4 v) {
        float4 o;
        o.x = __uint_as_float(f2tf32(v.x));
        o.y = __uint_as_float(f2tf32(v.y));
        o.z = __uint_as_float(f2tf32(v.z));
        o.w = __uint_as_float(f2tf32(v.w));
        *(float4*)dst = o;
    };

    // prologue: load & stage tile 0
    {
        aR0 = *(const float4*)(g_xn + (size_t)(rowBase + m0) * KDIM + kq0);
        aR1 = *(const float4*)(g_xn + (size_t)(rowBase + m1) * KDIM + kq1);
        int n0 = colBase + m0, n1 = colBase + m1;
        bR0 = (n0 < CCLS) ? *(const float4*)(W + (size_t)n0 * KDIM + kq0)
                          : make_float4(0, 0, 0, 0);
        bR1 = (n1 < CCLS) ? *(const float4*)(W + (size_t)n1 * KDIM + kq1)
                          : make_float4(0, 0, 0, 0);
        stage4(&As[0][m0 * LDSA + kq0], aR0);
        stage4(&As[0][m1 * LDSA + kq1], aR1);
        stage4(&Bs[0][m0 * LDSA + kq0], bR0);
        stage4(&Bs[0][m1 * LDSA + kq1], bR1);
    }
    __syncthreads();

    const int NKB = KDIM / BK;   // 32
    #pragma unroll 1
    for (int kb = 0; kb < NKB; ++kb) {
        const int buf = kb & 1;
        if (kb < NKB - 1) {
            int ko = (kb + 1) * BK;
            aR0 = *(const float4*)(g_xn + (size_t)(rowBase + m0) * KDIM + ko + kq0);
            aR1 = *(const float4*)(g_xn + (size_t)(rowBase + m1) * KDIM + ko + kq1);
            int n0 = colBase + m0, n1 = colBase + m1;
            bR0 = (n0 < CCLS) ? *(const float4*)(W + (size_t)n0 * KDIM + ko + kq0)
                              : make_float4(0, 0, 0, 0);
            bR1 = (n1 < CCLS) ? *(const float4*)(W + (size_t)n1 * KDIM + ko + kq1)
                              : make_float4(0, 0, 0, 0);
        }

        const float* Ab = As[buf];
        const float* Bb = Bs[buf];
        #pragma unroll
        for (int ks = 0; ks < 2; ++ks) {
            const int k0 = ks * 8;
            unsigned a[4][4], b[4][2];
            #pragma unroll
            for (int mi = 0; mi < 4; ++mi) {
                int m = warpM * 64 + mi * 16 + g;
                a[mi][0] = __float_as_uint(Ab[m * LDSA + k0 + t]);
                a[mi][1] = __float_as_uint(Ab[(m + 8) * LDSA + k0 + t]);
                a[mi][2] = __float_as_uint(Ab[m * LDSA + k0 + t + 4]);
                a[mi][3] = __float_as_uint(Ab[(m + 8) * LDSA + k0 + t + 4]);
            }
            #pragma unroll
            for (int ni = 0; ni < 4; ++ni) {
                int n = warpN * 32 + ni * 8 + g;
                b[ni][0] = __float_as_uint(Bb[n * LDSA + k0 + t]);
                b[ni][1] = __float_as_uint(Bb[n * LDSA + k0 + t + 4]);
            }
            #pragma unroll
            for (int mi = 0; mi < 4; ++mi)
                #pragma unroll
                for (int ni = 0; ni < 4; ++ni)
                    mma_tf32(acc[mi][ni], a[mi], b[ni]);
        }

        if (kb < NKB - 1) {
            float* Ad = As[buf ^ 1];
            float* Bd = Bs[buf ^ 1];
            stage4(&Ad[m0 * LDSA + kq0], aR0);
            stage4(&Ad[m1 * LDSA + kq1], aR1);
            stage4(&Bd[m0 * LDSA + kq0], bR0);
            stage4(&Bd[m1 * LDSA + kq1], bR1);
        }
        __syncthreads();
    }

    // epilogue: store wf, accumulate per-row exp sums
    #pragma unroll
    for (int mi = 0; mi < 4; ++mi) {
        int mG0 = rowBase + warpM * 64 + mi * 16 + g;
        int mG1 = mG0 + 8;
        float s0 = 0.0f, s1 = 0.0f;
        #pragma unroll
        for (int ni = 0; ni < 4; ++ni) {
            int nG = colBase + warpN * 32 + ni * 8 + 2 * t;
            float c0 = acc[mi][ni][0], c1 = acc[mi][ni][1];
            float c2 = acc[mi][ni][2], c3 = acc[mi][ni][3];
            if (nG < CCLS) {
                wf[(size_t)mG0 * CCLS + nG] = c0;
                wf[(size_t)mG1 * CCLS + nG] = c2;
                s0 += __expf(S_SCALE * c0);
                s1 += __expf(S_SCALE * c2);
            }
            if (nG + 1 < CCLS) {
                wf[(size_t)mG0 * CCLS + nG + 1] = c1;
                wf[(size_t)mG1 * CCLS + nG + 1] = c3;
                s0 += __expf(S_SCALE * c1);
                s1 += __expf(S_SCALE * c3);
            }
        }
        s0 += __shfl_xor_sync(0xffffffffu, s0, 1);
        s0 += __shfl_xor_sync(0xffffffffu, s0, 2);
        s1 += __shfl_xor_sync(0xffffffffu, s1, 1);
        s1 += __shfl_xor_sync(0xffffffffu, s1, 2);
        if (t == 0) {
            atomicAdd(&g_rowsum[mG0], s0);
            atomicAdd(&g_rowsum[mG1], s1);
        }
    }
}

// ---------------------------------------------------------------------------
// Kernel 3: arcface loss. One block, 1024 threads (one per sample).
// Labels dtype sniff: if every odd 32-bit word of the first 4KB is zero, the
// buffer is int64 (hi words of values < 2^31); otherwise int32.
// ---------------------------------------------------------------------------
__global__ void loss_kernel(const float* __restrict__ wf,
                            const int* __restrict__ labels_raw,
                            float* __restrict__ out, int lossIdx) {
    int i = threadIdx.x;   // 0..1023
    __shared__ int nzOdd;
    if (i == 0) nzOdd = 0;
    __syncthreads();
    if (i < 512 && labels_raw[2 * i + 1] != 0) atomicAdd(&nzOdd, 1);
    __syncthreads();

    int lab;
    if (nzOdd == 0) lab = (int)((const long long*)labels_raw)[i];   // int64
    else            lab = labels_raw[i];                            // int32

    float tgt = wf[(size_t)i * CCLS + lab];
    float tc  = fminf(fmaxf(tgt, -1.0f + EPS_CL), 1.0f - EPS_CL);
    float num = S_SCALE * cosf(acosf(tc) + MARGIN);
    float excl  = g_rowsum[i] - __expf(S_SCALE * tgt);
    float denom = __expf(num) + excl;
    float L = num - logf(denom);

    // block reduction of L over 1024 threads
    #pragma unroll
    for (int o = 16; o > 0; o >>= 1) L += __shfl_xor_sync(0xffffffffu, L, o);
    __shared__ float wsum[32];
    int lane = i & 31, wid = i >> 5;
    if (lane == 0) wsum[wid] = L;
    __syncthreads();
    if (wid == 0) {
        float v = wsum[lane];
        #pragma unroll
        for (int o = 16; o > 0; o >>= 1) v += __shfl_xor_sync(0xffffffffu, v, o);
        if (lane == 0) out[lossIdx] = -(v * (1.0f / 1024.0f));
    }
}

// ---------------------------------------------------------------------------
extern "C" void kernel_launch(void* const* d_in, const int* in_sizes, int n_in,
                              void* d_out, int out_size) {
    const float* x      = (const float*)d_in[0];   // [1024, 512] f32
    const float* W      = (const float*)d_in[1];   // [85742, 512] f32
    const int*   labels = (const int*)d_in[2];     // [1024] int32 or int64
    float* out = (float*)d_out;                    // wf [1024*85742] ++ loss

    normalize_kernel<<<MROWS, 128>>>(x);

    dim3 grid((CCLS + BN - 1) / BN, MROWS / BM);   // (670, 8)
    gemm_kernel<<<grid, 256>>>(W, out);

    loss_kernel<<<1, 1024>>>(out, labels, out, out_size - 1);
}

// round 6
// speedup vs baseline: 1.4632x; 1.4632x over previous
#include <cuda_runtime.h>
#include <cuda_fp16.h>
#include <math.h>
#include <stdint.h>

#define MROWS 1024
#define KDIM  512
#define CCLS  85742
#define S_SCALE 64.0f
#define MARGIN  0.5f
#define EPS_CL  1e-7f

// GEMM tiling: 256x128 CTA tile, 512 threads (16 warps, 4x4, warp tile 64x32)
#define BM 256
#define BN 128
#define BK 32                    // k-elements per stage
#define KSTAGES (KDIM / BK)      // 16
#define ROWB 64                  // bytes per smem row (32 halves), XOR-swizzled
#define A_BYTES (BM * ROWB)      // 16384
#define B_BYTES (BN * ROWB)      // 8192
// smem: [A0][A1][B0][B1] = 49152 bytes (static limit, no attribute needed)

__device__ float g_xn[MROWS * KDIM];
__device__ float g_rowsum[MROWS];

// ---------------------------------------------------------------------------
// helpers
// ---------------------------------------------------------------------------
__device__ __forceinline__ uint32_t smem_u32(const void* p) {
    uint32_t a;
    asm("{ .reg .u64 t; cvta.to.shared.u64 t, %1; cvt.u32.u64 %0, t; }"
        : "=r"(a) : "l"(p));
    return a;
}

// swizzled byte offset within a tile: row r, 16B-chunk c16 (0..3), low 8B sel
__device__ __forceinline__ uint32_t swz(int r, int c16) {
    return (uint32_t)(r * ROWB + ((c16 ^ ((r >> 1) & 3)) << 4));
}

__device__ __forceinline__ uint2 f4toh4(float4 v) {
    __half2 lo = __float22half2_rn(make_float2(v.x, v.y));
    __half2 hi = __float22half2_rn(make_float2(v.z, v.w));
    uint2 r;
    r.x = *reinterpret_cast<unsigned*>(&lo);
    r.y = *reinterpret_cast<unsigned*>(&hi);
    return r;
}

__device__ __forceinline__ void ldsm4(uint32_t* r, uint32_t addr) {
    asm volatile("ldmatrix.sync.aligned.m8n8.x4.shared.b16 {%0,%1,%2,%3}, [%4];"
                 : "=r"(r[0]), "=r"(r[1]), "=r"(r[2]), "=r"(r[3]) : "r"(addr));
}

__device__ __forceinline__ void mma_f16(float* d, const uint32_t* a,
                                        uint32_t b0, uint32_t b1) {
    asm volatile(
        "mma.sync.aligned.m16n8k16.row.col.f32.f16.f16.f32 "
        "{%0,%1,%2,%3}, {%4,%5,%6,%7}, {%8,%9}, {%0,%1,%2,%3};"
        : "+f"(d[0]), "+f"(d[1]), "+f"(d[2]), "+f"(d[3])
        : "r"(a[0]), "r"(a[1]), "r"(a[2]), "r"(a[3]), "r"(b0), "r"(b1));
}

// ---------------------------------------------------------------------------
// Kernel 1: L2-normalize rows of x into g_xn, zero g_rowsum.
// ---------------------------------------------------------------------------
__global__ void normalize_kernel(const float* __restrict__ x) {
    int row = blockIdx.x;
    int t   = threadIdx.x;                 // 128 threads, 4 floats each
    float4 v = ((const float4*)(x + (size_t)row * KDIM))[t];
    float s = v.x * v.x + v.y * v.y + v.z * v.z + v.w * v.w;
    #pragma unroll
    for (int o = 16; o > 0; o >>= 1) s += __shfl_xor_sync(0xffffffffu, s, o);
    __shared__ float ws[4];
    int lane = t & 31, wid = t >> 5;
    if (lane == 0) ws[wid] = s;
    __syncthreads();
    float tot = ws[0] + ws[1] + ws[2] + ws[3];
    float inv = 1.0f / fmaxf(sqrtf(tot), 1e-12f);
    float4 o4 = make_float4(v.x * inv, v.y * inv, v.z * inv, v.w * inv);
    ((float4*)(g_xn + (size_t)row * KDIM))[t] = o4;
    if (t == 0) g_rowsum[row] = 0.0f;
}

// ---------------------------------------------------------------------------
// Kernel 2: wf = xn @ W^T, fp16 m16n8k16 mma.sync + ldmatrix, double-buffered,
// fused per-row sum of exp(64*wf) via atomics.
// ---------------------------------------------------------------------------
__global__ __launch_bounds__(512, 1)
void gemm_f16(const float* __restrict__ W, float* __restrict__ wf) {
    __shared__ char smem[2 * A_BYTES + 2 * B_BYTES];   // 49152

    const int tid   = threadIdx.x;
    const int lane  = tid & 31;
    const int wid   = tid >> 5;
    const int warpM = wid & 3;     // 4 warps in M (64 rows each)
    const int warpN = wid >> 2;    // 4 warps in N (32 cols each)
    const int g     = lane >> 2;
    const int t     = lane & 3;
    const int rowBase = blockIdx.x * BM;
    const int colBase = blockIdx.y * BN;

    const uint32_t sbase = smem_u32(smem);

    float acc[4][4][4];
    #pragma unroll
    for (int mi = 0; mi < 4; ++mi)
        #pragma unroll
        for (int ni = 0; ni < 4; ++ni)
            #pragma unroll
            for (int r = 0; r < 4; ++r) acc[mi][ni][r] = 0.0f;

    // ldmatrix per-lane addressing: row-in-16-block and k-half selector
    const int rIn  = lane & 15;            // row within 16-row matrix group
    const int kHal = (lane >> 4);          // 0: k[0:8), 1: k[8:16) (16B chunk)

    float4 aR[4], bR[2];

    auto ldg_stage = [&](int ko) {
        #pragma unroll
        for (int i = 0; i < 4; ++i) {
            int s = i * 512 + tid, r = s >> 3, c = s & 7;
            aR[i] = *(const float4*)(g_xn + (size_t)(rowBase + r) * KDIM + ko + c * 4);
        }
        #pragma unroll
        for (int i = 0; i < 2; ++i) {
            int s = i * 512 + tid, r = s >> 3, c = s & 7;
            int n = colBase + r;
            bR[i] = (n < CCLS)
                ? *(const float4*)(W + (size_t)n * KDIM + ko + c * 4)
                : make_float4(0.f, 0.f, 0.f, 0.f);
        }
    };

    auto sts_stage = [&](int buf) {
        char* dA = smem + buf * A_BYTES;
        #pragma unroll
        for (int i = 0; i < 4; ++i) {
            int s = i * 512 + tid, r = s >> 3, c8 = s & 7;   // c8: 8B unit (4 halves)
            uint32_t off = swz(r, c8 >> 1) + (c8 & 1) * 8;
            *(uint2*)(dA + off) = f4toh4(aR[i]);
        }
        char* dB = smem + 2 * A_BYTES + buf * B_BYTES;
        #pragma unroll
        for (int i = 0; i < 2; ++i) {
            int s = i * 512 + tid, r = s >> 3, c8 = s & 7;
            uint32_t off = swz(r, c8 >> 1) + (c8 & 1) * 8;
            *(uint2*)(dB + off) = f4toh4(bR[i]);
        }
    };

    auto compute = [&](int buf) {
        const uint32_t aBase = sbase + buf * A_BYTES;
        const uint32_t bBase = sbase + 2 * A_BYTES + buf * B_BYTES;
        #pragma unroll
        for (int ks = 0; ks < 2; ++ks) {
            const int c16 = ks * 2 + kHal;           // 16B chunk index along k
            uint32_t af[4][4], bf[2][4];
            #pragma unroll
            for (int mi = 0; mi < 4; ++mi) {
                int row = warpM * 64 + mi * 16 + rIn;
                ldsm4(af[mi], aBase + swz(row, c16));
            }
            #pragma unroll
            for (int nb = 0; nb < 2; ++nb) {
                int row = warpN * 32 + nb * 16 + rIn;
                ldsm4(bf[nb], bBase + swz(row, c16));
            }
            #pragma unroll
            for (int mi = 0; mi < 4; ++mi)
                #pragma unroll
                for (int ni = 0; ni < 4; ++ni)
                    mma_f16(acc[mi][ni], af[mi],
                            bf[ni >> 1][ni & 1], bf[ni >> 1][(ni & 1) + 2]);
        }
    };

    // prologue
    ldg_stage(0);
    sts_stage(0);
    __syncthreads();

    #pragma unroll 1
    for (int kb = 0; kb < KSTAGES; ++kb) {
        const int buf = kb & 1;
        if (kb < KSTAGES - 1) ldg_stage((kb + 1) * BK);
        compute(buf);
        if (kb < KSTAGES - 1) sts_stage(buf ^ 1);
        __syncthreads();
    }

    // epilogue: store wf (32B-sector coalesced per row), fused exp rowsums
    #pragma unroll
    for (int mi = 0; mi < 4; ++mi) {
        int mG0 = rowBase + warpM * 64 + mi * 16 + g;
        int mG1 = mG0 + 8;
        float s0 = 0.0f, s1 = 0.0f;
        #pragma unroll
        for (int ni = 0; ni < 4; ++ni) {
            int nG = colBase + warpN * 32 + ni * 8 + 2 * t;
            float c0 = acc[mi][ni][0], c1 = acc[mi][ni][1];
            float c2 = acc[mi][ni][2], c3 = acc[mi][ni][3];
            if (nG < CCLS) {
                wf[(size_t)mG0 * CCLS + nG] = c0;
                wf[(size_t)mG1 * CCLS + nG] = c2;
                s0 += __expf(S_SCALE * c0);
                s1 += __expf(S_SCALE * c2);
            }
            if (nG + 1 < CCLS) {
                wf[(size_t)mG0 * CCLS + nG + 1] = c1;
                wf[(size_t)mG1 * CCLS + nG + 1] = c3;
                s0 += __expf(S_SCALE * c1);
                s1 += __expf(S_SCALE * c3);
            }
        }
        s0 += __shfl_xor_sync(0xffffffffu, s0, 1);
        s0 += __shfl_xor_sync(0xffffffffu, s0, 2);
        s1 += __shfl_xor_sync(0xffffffffu, s1, 1);
        s1 += __shfl_xor_sync(0xffffffffu, s1, 2);
        if (t == 0) {
            atomicAdd(&g_rowsum[mG0], s0);
            atomicAdd(&g_rowsum[mG1], s1);
        }
    }
}

// ---------------------------------------------------------------------------
// Kernel 3: arcface loss. One block, 1024 threads (one per sample).
// Labels dtype sniff: all odd 32-bit words zero => int64.
// ---------------------------------------------------------------------------
__global__ void loss_kernel(const float* __restrict__ wf,
                            const int* __restrict__ labels_raw,
                            float* __restrict__ out, int lossIdx) {
    int i = threadIdx.x;   // 0..1023
    __shared__ int nzOdd;
    if (i == 0) nzOdd = 0;
    __syncthreads();
    if (i < 512 && labels_raw[2 * i + 1] != 0) atomicAdd(&nzOdd, 1);
    __syncthreads();

    int lab;
    if (nzOdd == 0) lab = (int)((const long long*)labels_raw)[i];   // int64
    else            lab = labels_raw[i];                            // int32

    float tgt = wf[(size_t)i * CCLS + lab];
    float tc  = fminf(fmaxf(tgt, -1.0f + EPS_CL), 1.0f - EPS_CL);
    float num = S_SCALE * cosf(acosf(tc) + MARGIN);
    float excl  = g_rowsum[i] - __expf(S_SCALE * tgt);
    float denom = __expf(num) + excl;
    float L = num - logf(denom);

    #pragma unroll
    for (int o = 16; o > 0; o >>= 1) L += __shfl_xor_sync(0xffffffffu, L, o);
    __shared__ float wsum[32];
    int lane = i & 31, wid = i >> 5;
    if (lane == 0) wsum[wid] = L;
    __syncthreads();
    if (wid == 0) {
        float v = wsum[lane];
        #pragma unroll
        for (int o = 16; o > 0; o >>= 1) v += __shfl_xor_sync(0xffffffffu, v, o);
        if (lane == 0) out[lossIdx] = -(v * (1.0f / 1024.0f));
    }
}

// ---------------------------------------------------------------------------
extern "C" void kernel_launch(void* const* d_in, const int* in_sizes, int n_in,
                              void* d_out, int out_size) {
    const float* x      = (const float*)d_in[0];   // [1024, 512] f32
    const float* W      = (const float*)d_in[1];   // [85742, 512] f32
    const int*   labels = (const int*)d_in[2];     // [1024] int32 or int64
    float* out = (float*)d_out;                    // wf [1024*85742] ++ loss

    normalize_kernel<<<MROWS, 128>>>(x);

    // x = M tiles (4, fast-varying -> CTAs sharing a W col-tile run adjacently)
    dim3 grid(MROWS / BM, (CCLS + BN - 1) / BN);   // (4, 670)
    gemm_f16<<<grid, 512>>>(W, out);

    loss_kernel<<<1, 1024>>>(out, labels, out, out_size - 1);
}

// round 7
// speedup vs baseline: 1.5700x; 1.0730x over previous
#include <cuda_runtime.h>
#include <cuda_fp16.h>
#include <math.h>
#include <stdint.h>

#define MROWS 1024
#define KDIM  512
#define CCLS  85742
#define S_SCALE 64.0f
#define MARGIN  0.5f
#define EPS_CL  1e-7f

// GEMM tiling: 256x128 CTA tile, 512 threads (16 warps, 4 M x 4 N, warp 64x32)
#define BM 256
#define BN 128
#define BK 32                    // k-halves per stage -> 64B per smem row
#define KSTAGES (KDIM / BK)      // 16
#define ROWB 64                  // bytes per smem row, XOR-swizzled in 16B chunks
#define AST (BM * ROWB)          // 16384
#define BST (BN * ROWB)          // 8192
#define STAGE_BYTES (AST + BST)  // 24576
#define NSTAGE 3                 // cp.async pipeline depth (72KB dynamic smem)

__device__ __half g_xnh[MROWS * KDIM];          // normalized x, fp16
__device__ __half g_wh[(size_t)CCLS * KDIM];    // W, fp16 (87.8 MB)
__device__ float  g_rowsum[MROWS];

// ---------------------------------------------------------------------------
// helpers
// ---------------------------------------------------------------------------
__device__ __forceinline__ uint32_t smem_u32(const void* p) {
    uint32_t a;
    asm("{ .reg .u64 t; cvta.to.shared.u64 t, %1; cvt.u32.u64 %0, t; }"
        : "=r"(a) : "l"(p));
    return a;
}

// swizzled byte offset within a tile: row r, 16B chunk c16 (0..3)
__device__ __forceinline__ uint32_t swz(int r, int c16) {
    return (uint32_t)(r * ROWB + ((c16 ^ ((r >> 1) & 3)) << 4));
}

__device__ __forceinline__ uint2 f4toh4(float4 v) {
    __half2 lo = __float22half2_rn(make_float2(v.x, v.y));
    __half2 hi = __float22half2_rn(make_float2(v.z, v.w));
    uint2 r;
    r.x = *reinterpret_cast<unsigned*>(&lo);
    r.y = *reinterpret_cast<unsigned*>(&hi);
    return r;
}

__device__ __forceinline__ void cp16(uint32_t dst, const void* src, uint32_t srcsz) {
    asm volatile("cp.async.cg.shared.global [%0], [%1], 16, %2;"
                 :: "r"(dst), "l"(src), "r"(srcsz) : "memory");
}
__device__ __forceinline__ void cp_commit() {
    asm volatile("cp.async.commit_group;" ::: "memory");
}
template <int N> __device__ __forceinline__ void cp_wait() {
    asm volatile("cp.async.wait_group %0;" :: "n"(N) : "memory");
}

__device__ __forceinline__ void ldsm4(uint32_t* r, uint32_t addr) {
    asm volatile("ldmatrix.sync.aligned.m8n8.x4.shared.b16 {%0,%1,%2,%3}, [%4];"
                 : "=r"(r[0]), "=r"(r[1]), "=r"(r[2]), "=r"(r[3]) : "r"(addr));
}

__device__ __forceinline__ void mma_f16(float* d, const uint32_t* a,
                                        uint32_t b0, uint32_t b1) {
    asm volatile(
        "mma.sync.aligned.m16n8k16.row.col.f32.f16.f16.f32 "
        "{%0,%1,%2,%3}, {%4,%5,%6,%7}, {%8,%9}, {%0,%1,%2,%3};"
        : "+f"(d[0]), "+f"(d[1]), "+f"(d[2]), "+f"(d[3])
        : "r"(a[0]), "r"(a[1]), "r"(a[2]), "r"(a[3]), "r"(b0), "r"(b1));
}

// ---------------------------------------------------------------------------
// Kernel 1: L2-normalize rows of x -> g_xnh (fp16), zero g_rowsum.
// ---------------------------------------------------------------------------
__global__ void normalize_kernel(const float* __restrict__ x) {
    int row = blockIdx.x;
    int t   = threadIdx.x;                 // 128 threads, 4 floats each
    float4 v = ((const float4*)(x + (size_t)row * KDIM))[t];
    float s = v.x * v.x + v.y * v.y + v.z * v.z + v.w * v.w;
    #pragma unroll
    for (int o = 16; o > 0; o >>= 1) s += __shfl_xor_sync(0xffffffffu, s, o);
    __shared__ float ws[4];
    int lane = t & 31, wid = t >> 5;
    if (lane == 0) ws[wid] = s;
    __syncthreads();
    float tot = ws[0] + ws[1] + ws[2] + ws[3];
    float inv = 1.0f / fmaxf(sqrtf(tot), 1e-12f);
    float4 o4 = make_float4(v.x * inv, v.y * inv, v.z * inv, v.w * inv);
    ((uint2*)(g_xnh + (size_t)row * KDIM))[t] = f4toh4(o4);
    if (t == 0) g_rowsum[row] = 0.0f;
}

// ---------------------------------------------------------------------------
// Kernel 1b: convert W (f32) -> g_wh (fp16). 8 elements per thread.
// ---------------------------------------------------------------------------
__global__ void convw_kernel(const float* __restrict__ W) {
    size_t i8 = (size_t)blockIdx.x * blockDim.x + threadIdx.x;
    if (i8 >= (size_t)CCLS * KDIM / 8) return;
    float4 a = ((const float4*)W)[i8 * 2];
    float4 b = ((const float4*)W)[i8 * 2 + 1];
    uint2 lo = f4toh4(a), hi = f4toh4(b);
    ((uint4*)g_wh)[i8] = make_uint4(lo.x, lo.y, hi.x, hi.y);
}

// ---------------------------------------------------------------------------
// Kernel 2: wf = xn @ W^T, fp16 m16n8k16 mma.sync + ldmatrix, cp.async
// 3-stage pipeline, fused per-row sum of exp(64*wf) via atomics.
// ---------------------------------------------------------------------------
__global__ __launch_bounds__(512, 1)
void gemm_f16(float* __restrict__ wf) {
    extern __shared__ char smem[];

    const int tid   = threadIdx.x;
    const int lane  = tid & 31;
    const int wid   = tid >> 5;
    const int warpM = wid & 3;     // 4 warps in M (64 rows each)
    const int warpN = wid >> 2;    // 4 warps in N (32 cols each)
    const int g     = lane >> 2;
    const int t     = lane & 3;
    const int rowBase = blockIdx.x * BM;
    const int colBase = blockIdx.y * BN;

    const uint32_t sbase = smem_u32(smem);

    float acc[4][4][4];
    #pragma unroll
    for (int mi = 0; mi < 4; ++mi)
        #pragma unroll
        for (int ni = 0; ni < 4; ++ni)
            #pragma unroll
            for (int r = 0; r < 4; ++r) acc[mi][ni][r] = 0.0f;

    // per-thread cp.async source/dest mapping (16B chunks)
    const int rA0 = tid >> 2,           cA0 = tid & 3;
    const int rA1 = (tid + 512) >> 2,   cA1 = tid & 3;   // (tid+512)&3 == tid&3
    const int rB  = tid >> 2,           cB  = tid & 3;
    const __half* gA0 = g_xnh + (size_t)(rowBase + rA0) * KDIM + cA0 * 8;
    const __half* gA1 = g_xnh + (size_t)(rowBase + rA1) * KDIM + cA1 * 8;
    const int nB = colBase + rB;
    const bool bOk = nB < CCLS;
    const __half* gB = g_wh + (bOk ? (size_t)nB * KDIM + cB * 8 : 0);
    const uint32_t bSz = bOk ? 16u : 0u;
    const uint32_t dA0 = swz(rA0, cA0), dA1 = swz(rA1, cA1);
    const uint32_t dB  = AST + swz(rB, cB);

    auto cp_stage = [&](int slot, int ko) {
        uint32_t base = sbase + slot * STAGE_BYTES;
        cp16(base + dA0, gA0 + ko, 16);
        cp16(base + dA1, gA1 + ko, 16);
        cp16(base + dB,  gB  + ko, bSz);
    };

    // ldmatrix per-lane addressing
    const int rIn  = lane & 15;
    const int kHal = lane >> 4;

    auto compute = [&](int slot) {
        const uint32_t aBase = sbase + slot * STAGE_BYTES;
        const uint32_t bBase = aBase + AST;
        #pragma unroll
        for (int ks = 0; ks < 2; ++ks) {
            const int c16 = ks * 2 + kHal;
            uint32_t af[4][4], bf[2][4];
            #pragma unroll
            for (int mi = 0; mi < 4; ++mi)
                ldsm4(af[mi], aBase + swz(warpM * 64 + mi * 16 + rIn, c16));
            #pragma unroll
            for (int nb = 0; nb < 2; ++nb)
                ldsm4(bf[nb], bBase + swz(warpN * 32 + nb * 16 + rIn, c16));
            #pragma unroll
            for (int mi = 0; mi < 4; ++mi)
                #pragma unroll
                for (int ni = 0; ni < 4; ++ni)
                    mma_f16(acc[mi][ni], af[mi],
                            bf[ni >> 1][ni & 1], bf[ni >> 1][(ni & 1) + 2]);
        }
    };

    // prologue: fill stages 0,1
    cp_stage(0, 0);  cp_commit();
    cp_stage(1, BK); cp_commit();

    #pragma unroll 1
    for (int kb = 0; kb < KSTAGES; ++kb) {
        cp_wait<1>();          // stage kb arrived
        __syncthreads();       // visible to all warps; prior compute done
        if (kb + 2 < KSTAGES) cp_stage((kb + 2) % NSTAGE, (kb + 2) * BK);
        cp_commit();           // keep group counting uniform
        compute(kb % NSTAGE);
    }

    // epilogue: store wf (coalesced 32B sectors), fused exp rowsums
    #pragma unroll
    for (int mi = 0; mi < 4; ++mi) {
        int mG0 = rowBase + warpM * 64 + mi * 16 + g;
        int mG1 = mG0 + 8;
        float s0 = 0.0f, s1 = 0.0f;
        #pragma unroll
        for (int ni = 0; ni < 4; ++ni) {
            int nG = colBase + warpN * 32 + ni * 8 + 2 * t;
            float c0 = acc[mi][ni][0], c1 = acc[mi][ni][1];
            float c2 = acc[mi][ni][2], c3 = acc[mi][ni][3];
            if (nG < CCLS) {
                wf[(size_t)mG0 * CCLS + nG] = c0;
                wf[(size_t)mG1 * CCLS + nG] = c2;
                s0 += __expf(S_SCALE * c0);
                s1 += __expf(S_SCALE * c2);
            }
            if (nG + 1 < CCLS) {
                wf[(size_t)mG0 * CCLS + nG + 1] = c1;
                wf[(size_t)mG1 * CCLS + nG + 1] = c3;
                s0 += __expf(S_SCALE * c1);
                s1 += __expf(S_SCALE * c3);
            }
        }
        s0 += __shfl_xor_sync(0xffffffffu, s0, 1);
        s0 += __shfl_xor_sync(0xffffffffu, s0, 2);
        s1 += __shfl_xor_sync(0xffffffffu, s1, 1);
        s1 += __shfl_xor_sync(0xffffffffu, s1, 2);
        if (t == 0) {
            atomicAdd(&g_rowsum[mG0], s0);
            atomicAdd(&g_rowsum[mG1], s1);
        }
    }
}

// ---------------------------------------------------------------------------
// Kernel 3: arcface loss. One block, 1024 threads (one per sample).
// Labels dtype sniff: all odd 32-bit words zero => int64.
// ---------------------------------------------------------------------------
__global__ void loss_kernel(const float* __restrict__ wf,
                            const int* __restrict__ labels_raw,
                            float* __restrict__ out, int lossIdx) {
    int i = threadIdx.x;   // 0..1023
    __shared__ int nzOdd;
    if (i == 0) nzOdd = 0;
    __syncthreads();
    if (i < 512 && labels_raw[2 * i + 1] != 0) atomicAdd(&nzOdd, 1);
    __syncthreads();

    int lab;
    if (nzOdd == 0) lab = (int)((const long long*)labels_raw)[i];   // int64
    else            lab = labels_raw[i];                            // int32

    float tgt = wf[(size_t)i * CCLS + lab];
    float tc  = fminf(fmaxf(tgt, -1.0f + EPS_CL), 1.0f - EPS_CL);
    float num = S_SCALE * cosf(acosf(tc) + MARGIN);
    float excl  = g_rowsum[i] - __expf(S_SCALE * tgt);
    float denom = __expf(num) + excl;
    float L = num - logf(denom);

    #pragma unroll
    for (int o = 16; o > 0; o >>= 1) L += __shfl_xor_sync(0xffffffffu, L, o);
    __shared__ float wsum[32];
    int lane = i & 31, wid = i >> 5;
    if (lane == 0) wsum[wid] = L;
    __syncthreads();
    if (wid == 0) {
        float v = wsum[lane];
        #pragma unroll
        for (int o = 16; o > 0; o >>= 1) v += __shfl_xor_sync(0xffffffffu, v, o);
        if (lane == 0) out[lossIdx] = -(v * (1.0f / 1024.0f));
    }
}

// ---------------------------------------------------------------------------
extern "C" void kernel_launch(void* const* d_in, const int* in_sizes, int n_in,
                              void* d_out, int out_size) {
    const float* x      = (const float*)d_in[0];   // [1024, 512] f32
    const float* W      = (const float*)d_in[1];   // [85742, 512] f32
    const int*   labels = (const int*)d_in[2];     // [1024] int32 or int64
    float* out = (float*)d_out;                    // wf [1024*85742] ++ loss

    normalize_kernel<<<MROWS, 128>>>(x);

    int n8 = (int)((size_t)CCLS * KDIM / 8);
    convw_kernel<<<(n8 + 255) / 256, 256>>>(W);

    cudaFuncSetAttribute(gemm_f16, cudaFuncAttributeMaxDynamicSharedMemorySize,
                         NSTAGE * STAGE_BYTES);
    dim3 grid(MROWS / BM, (CCLS + BN - 1) / BN);   // (4, 670), M fast
    gemm_f16<<<grid, 512, NSTAGE * STAGE_BYTES>>>(out);

    loss_kernel<<<1, 1024>>>(out, labels, out, out_size - 1);
}

// round 8
// speedup vs baseline: 2.5240x; 1.6076x over previous
#include <cuda_runtime.h>
#include <cuda_fp16.h>
#include <math.h>
#include <stdint.h>

#define MROWS 1024
#define KDIM  512
#define CCLS  85742
#define S_SCALE 64.0f
#define MARGIN  0.5f
#define EPS_CL  1e-7f

// GEMM tiling: 128x128 CTA tile, 256 threads (8 warps, 2 M x 4 N, warp 64x32)
// occupancy 2 CTAs/SM.
#define BM 128
#define BN 128
#define BK 64                    // k-halves per stage -> 128B per smem row
#define KSTAGES (KDIM / BK)      // 8
#define ROWB 128                 // bytes per smem row (SW128 swizzle)
#define AST (BM * ROWB)          // 16384
#define BST (BN * ROWB)          // 16384
#define STAGE_BYTES (AST + BST)  // 32768
#define NSTAGE 3                 // 96KB dynamic smem per CTA

__device__ __half g_xnh[MROWS * KDIM];          // normalized x, fp16
__device__ __half g_wh[(size_t)CCLS * KDIM];    // W, fp16 (87.8 MB)
__device__ float  g_rowsum[MROWS];

// ---------------------------------------------------------------------------
// helpers
// ---------------------------------------------------------------------------
__device__ __forceinline__ uint32_t smem_u32(const void* p) {
    uint32_t a;
    asm("{ .reg .u64 t; cvta.to.shared.u64 t, %1; cvt.u32.u64 %0, t; }"
        : "=r"(a) : "l"(p));
    return a;
}

// SW128 swizzle: row r (128B rows), 16B chunk c in [0,8)
__device__ __forceinline__ uint32_t swz(int r, int c) {
    return (uint32_t)(r * ROWB + ((c ^ (r & 7)) << 4));
}

__device__ __forceinline__ uint2 f4toh4(float4 v) {
    __half2 lo = __float22half2_rn(make_float2(v.x, v.y));
    __half2 hi = __float22half2_rn(make_float2(v.z, v.w));
    uint2 r;
    r.x = *reinterpret_cast<unsigned*>(&lo);
    r.y = *reinterpret_cast<unsigned*>(&hi);
    return r;
}

__device__ __forceinline__ void cp16(uint32_t dst, const void* src, uint32_t srcsz) {
    asm volatile("cp.async.cg.shared.global [%0], [%1], 16, %2;"
                 :: "r"(dst), "l"(src), "r"(srcsz) : "memory");
}
__device__ __forceinline__ void cp_commit() {
    asm volatile("cp.async.commit_group;" ::: "memory");
}
template <int N> __device__ __forceinline__ void cp_wait() {
    asm volatile("cp.async.wait_group %0;" :: "n"(N) : "memory");
}

__device__ __forceinline__ void ldsm4(uint32_t* r, uint32_t addr) {
    asm volatile("ldmatrix.sync.aligned.m8n8.x4.shared.b16 {%0,%1,%2,%3}, [%4];"
                 : "=r"(r[0]), "=r"(r[1]), "=r"(r[2]), "=r"(r[3]) : "r"(addr));
}

__device__ __forceinline__ void mma_f16(float* d, const uint32_t* a,
                                        uint32_t b0, uint32_t b1) {
    asm volatile(
        "mma.sync.aligned.m16n8k16.row.col.f32.f16.f16.f32 "
        "{%0,%1,%2,%3}, {%4,%5,%6,%7}, {%8,%9}, {%0,%1,%2,%3};"
        : "+f"(d[0]), "+f"(d[1]), "+f"(d[2]), "+f"(d[3])
        : "r"(a[0]), "r"(a[1]), "r"(a[2]), "r"(a[3]), "r"(b0), "r"(b1));
}

// ---------------------------------------------------------------------------
// Kernel 1: L2-normalize rows of x -> g_xnh (fp16), zero g_rowsum.
// ---------------------------------------------------------------------------
__global__ void normalize_kernel(const float* __restrict__ x) {
    int row = blockIdx.x;
    int t   = threadIdx.x;                 // 128 threads, 4 floats each
    float4 v = ((const float4*)(x + (size_t)row * KDIM))[t];
    float s = v.x * v.x + v.y * v.y + v.z * v.z + v.w * v.w;
    #pragma unroll
    for (int o = 16; o > 0; o >>= 1) s += __shfl_xor_sync(0xffffffffu, s, o);
    __shared__ float ws[4];
    int lane = t & 31, wid = t >> 5;
    if (lane == 0) ws[wid] = s;
    __syncthreads();
    float tot = ws[0] + ws[1] + ws[2] + ws[3];
    float inv = 1.0f / fmaxf(sqrtf(tot), 1e-12f);
    float4 o4 = make_float4(v.x * inv, v.y * inv, v.z * inv, v.w * inv);
    ((uint2*)(g_xnh + (size_t)row * KDIM))[t] = f4toh4(o4);
    if (t == 0) g_rowsum[row] = 0.0f;
}

// ---------------------------------------------------------------------------
// Kernel 1b: convert W (f32) -> g_wh (fp16). 8 elements per thread.
// ---------------------------------------------------------------------------
__global__ void convw_kernel(const float* __restrict__ W) {
    size_t i8 = (size_t)blockIdx.x * blockDim.x + threadIdx.x;
    if (i8 >= (size_t)CCLS * KDIM / 8) return;
    float4 a = ((const float4*)W)[i8 * 2];
    float4 b = ((const float4*)W)[i8 * 2 + 1];
    uint2 lo = f4toh4(a), hi = f4toh4(b);
    ((uint4*)g_wh)[i8] = make_uint4(lo.x, lo.y, hi.x, hi.y);
}

// ---------------------------------------------------------------------------
// Kernel 2: wf = xn @ W^T, fp16 m16n8k16 mma.sync + ldmatrix, cp.async
// 3-stage pipeline, occupancy 2, fused per-row exp sums via atomics.
// ---------------------------------------------------------------------------
__global__ __launch_bounds__(256, 2)
void gemm_f16(float* __restrict__ wf) {
    extern __shared__ char smem[];

    const int tid   = threadIdx.x;
    const int lane  = tid & 31;
    const int wid   = tid >> 5;
    const int warpM = wid & 1;     // 2 warps in M (64 rows each)
    const int warpN = wid >> 1;    // 4 warps in N (32 cols each)
    const int g     = lane >> 2;
    const int t     = lane & 3;
    const int rowBase = blockIdx.x * BM;
    const int colBase = blockIdx.y * BN;

    const uint32_t sbase = smem_u32(smem);

    float acc[4][4][4];
    #pragma unroll
    for (int mi = 0; mi < 4; ++mi)
        #pragma unroll
        for (int ni = 0; ni < 4; ++ni)
            #pragma unroll
            for (int r = 0; r < 4; ++r) acc[mi][ni][r] = 0.0f;

    // cp.async mapping: 1024 16B-chunks per operand tile, 4 per thread
    // s = i*256 + tid; r = s>>3 (row), c = s&7 (16B chunk)
    const int cS = tid & 7;
    uint32_t dA[4], dB[4];
    const __half* gA[4];
    const __half* gB[4];
    uint32_t bSz[4];
    #pragma unroll
    for (int i = 0; i < 4; ++i) {
        int s = i * 256 + tid, r = s >> 3;
        dA[i] = swz(r, cS);
        dB[i] = AST + swz(r, cS);
        gA[i] = g_xnh + (size_t)(rowBase + r) * KDIM + cS * 8;
        int n = colBase + r;
        bool ok = n < CCLS;
        gB[i] = g_wh + (ok ? (size_t)n * KDIM + cS * 8 : 0);
        bSz[i] = ok ? 16u : 0u;
    }

    auto cp_stage = [&](int slot, int ko) {
        uint32_t base = sbase + slot * STAGE_BYTES;
        #pragma unroll
        for (int i = 0; i < 4; ++i) cp16(base + dA[i], gA[i] + ko, 16);
        #pragma unroll
        for (int i = 0; i < 4; ++i) cp16(base + dB[i], gB[i] + ko, bSz[i]);
    };

    // ldmatrix per-lane addressing
    const int rIn  = lane & 15;
    const int kHal = lane >> 4;

    auto compute = [&](int slot) {
        const uint32_t aBase = sbase + slot * STAGE_BYTES;
        const uint32_t bBase = aBase + AST;
        #pragma unroll
        for (int ks = 0; ks < 4; ++ks) {
            const int c16 = ks * 2 + kHal;
            uint32_t af[4][4], bf[2][4];
            #pragma unroll
            for (int mi = 0; mi < 4; ++mi)
                ldsm4(af[mi], aBase + swz(warpM * 64 + mi * 16 + rIn, c16));
            #pragma unroll
            for (int nb = 0; nb < 2; ++nb)
                ldsm4(bf[nb], bBase + swz(warpN * 32 + nb * 16 + rIn, c16));
            #pragma unroll
            for (int mi = 0; mi < 4; ++mi)
                #pragma unroll
                for (int ni = 0; ni < 4; ++ni)
                    mma_f16(acc[mi][ni], af[mi],
                            bf[ni >> 1][ni & 1], bf[ni >> 1][(ni & 1) + 2]);
        }
    };

    // prologue: fill stages 0,1
    cp_stage(0, 0);  cp_commit();
    cp_stage(1, BK); cp_commit();

    #pragma unroll 1
    for (int kb = 0; kb < KSTAGES; ++kb) {
        cp_wait<1>();          // stage kb arrived
        __syncthreads();       // visible to all warps; prior compute done
        if (kb + 2 < KSTAGES) cp_stage((kb + 2) % NSTAGE, (kb + 2) * BK);
        cp_commit();           // keep group counting uniform
        compute(kb % NSTAGE);
    }

    // epilogue: float2 stores (nG even & CCLS even -> pair fully valid) +
    // fused exp rowsums
    #pragma unroll
    for (int mi = 0; mi < 4; ++mi) {
        int mG0 = rowBase + warpM * 64 + mi * 16 + g;
        int mG1 = mG0 + 8;
        float s0 = 0.0f, s1 = 0.0f;
        #pragma unroll
        for (int ni = 0; ni < 4; ++ni) {
            int nG = colBase + warpN * 32 + ni * 8 + 2 * t;
            float c0 = acc[mi][ni][0], c1 = acc[mi][ni][1];
            float c2 = acc[mi][ni][2], c3 = acc[mi][ni][3];
            if (nG < CCLS) {
                *(float2*)(wf + (size_t)mG0 * CCLS + nG) = make_float2(c0, c1);
                *(float2*)(wf + (size_t)mG1 * CCLS + nG) = make_float2(c2, c3);
                s0 += __expf(S_SCALE * c0) + __expf(S_SCALE * c1);
                s1 += __expf(S_SCALE * c2) + __expf(S_SCALE * c3);
            }
        }
        s0 += __shfl_xor_sync(0xffffffffu, s0, 1);
        s0 += __shfl_xor_sync(0xffffffffu, s0, 2);
        s1 += __shfl_xor_sync(0xffffffffu, s1, 1);
        s1 += __shfl_xor_sync(0xffffffffu, s1, 2);
        if (t == 0) {
            atomicAdd(&g_rowsum[mG0], s0);
            atomicAdd(&g_rowsum[mG1], s1);
        }
    }
}

// ---------------------------------------------------------------------------
// Kernel 3: arcface loss. One block, 1024 threads (one per sample).
// Labels dtype sniff: all odd 32-bit words zero => int64.
// ---------------------------------------------------------------------------
__global__ void loss_kernel(const float* __restrict__ wf,
                            const int* __restrict__ labels_raw,
                            float* __restrict__ out, int lossIdx) {
    int i = threadIdx.x;   // 0..1023
    __shared__ int nzOdd;
    if (i == 0) nzOdd = 0;
    __syncthreads();
    if (i < 512 && labels_raw[2 * i + 1] != 0) atomicAdd(&nzOdd, 1);
    __syncthreads();

    int lab;
    if (nzOdd == 0) lab = (int)((const long long*)labels_raw)[i];   // int64
    else            lab = labels_raw[i];                            // int32

    float tgt = wf[(size_t)i * CCLS + lab];
    float tc  = fminf(fmaxf(tgt, -1.0f + EPS_CL), 1.0f - EPS_CL);
    float num = S_SCALE * cosf(acosf(tc) + MARGIN);
    float excl  = g_rowsum[i] - __expf(S_SCALE * tgt);
    float denom = __expf(num) + excl;
    float L = num - logf(denom);

    #pragma unroll
    for (int o = 16; o > 0; o >>= 1) L += __shfl_xor_sync(0xffffffffu, L, o);
    __shared__ float wsum[32];
    int lane = i & 31, wid = i >> 5;
    if (lane == 0) wsum[wid] = L;
    __syncthreads();
    if (wid == 0) {
        float v = wsum[lane];
        #pragma unroll
        for (int o = 16; o > 0; o >>= 1) v += __shfl_xor_sync(0xffffffffu, v, o);
        if (lane == 0) out[lossIdx] = -(v * (1.0f / 1024.0f));
    }
}

// ---------------------------------------------------------------------------
extern "C" void kernel_launch(void* const* d_in, const int* in_sizes, int n_in,
                              void* d_out, int out_size) {
    const float* x      = (const float*)d_in[0];   // [1024, 512] f32
    const float* W      = (const float*)d_in[1];   // [85742, 512] f32
    const int*   labels = (const int*)d_in[2];     // [1024] int32 or int64
    float* out = (float*)d_out;                    // wf [1024*85742] ++ loss

    normalize_kernel<<<MROWS, 128>>>(x);

    int n8 = (int)((size_t)CCLS * KDIM / 8);
    convw_kernel<<<(n8 + 255) / 256, 256>>>(W);

    cudaFuncSetAttribute(gemm_f16, cudaFuncAttributeMaxDynamicSharedMemorySize,
                         NSTAGE * STAGE_BYTES);
    dim3 grid(MROWS / BM, (CCLS + BN - 1) / BN);   // (8, 670), M fast
    gemm_f16<<<grid, 256, NSTAGE * STAGE_BYTES>>>(out);

    loss_kernel<<<1, 1024>>>(out, labels, out, out_size - 1);
}

// round 9
// speedup vs baseline: 2.5303x; 1.0025x over previous
#include <cuda_runtime.h>
#include <cuda_fp16.h>
#include <math.h>
#include <stdint.h>

#define MROWS 1024
#define KDIM  512
#define CCLS  85742
#define S_SCALE 64.0f
#define MARGIN  0.5f
#define EPS_CL  1e-7f

// GEMM tiling: 128x128 CTA tile, 256 threads (8 warps, 2 M x 4 N, warp 64x32)
// occupancy 2 CTAs/SM.
#define BM 128
#define BN 128
#define BK 64                    // k-halves per stage -> 128B per smem row
#define KSTAGES (KDIM / BK)      // 8
#define ROWB 128                 // bytes per smem row (SW128 swizzle)
#define AST (BM * ROWB)          // 16384
#define BST (BN * ROWB)          // 16384
#define STAGE_BYTES (AST + BST)  // 32768
#define NSTAGE 3                 // 96KB dynamic smem per CTA

#define NCHUNK8 ((size_t)CCLS * KDIM / 8)        // 16B-output chunks of W
#define CONVBLK ((int)((NCHUNK8 + 255) / 256))   // conv blocks (256 thr)

__device__ __half g_xnh[MROWS * KDIM];          // normalized x, fp16
__device__ __half g_wh[(size_t)CCLS * KDIM];    // W, fp16 (87.8 MB)
__device__ float  g_rowsum[MROWS];
__device__ float  g_loss;
__device__ int    g_isI64;

// ---------------------------------------------------------------------------
// helpers
// ---------------------------------------------------------------------------
__device__ __forceinline__ uint32_t smem_u32(const void* p) {
    uint32_t a;
    asm("{ .reg .u64 t; cvta.to.shared.u64 t, %1; cvt.u32.u64 %0, t; }"
        : "=r"(a) : "l"(p));
    return a;
}

// SW128 swizzle: row r (128B rows), 16B chunk c in [0,8)
__device__ __forceinline__ uint32_t swz(int r, int c) {
    return (uint32_t)(r * ROWB + ((c ^ (r & 7)) << 4));
}

__device__ __forceinline__ uint2 f4toh4(float4 v) {
    __half2 lo = __float22half2_rn(make_float2(v.x, v.y));
    __half2 hi = __float22half2_rn(make_float2(v.z, v.w));
    uint2 r;
    r.x = *reinterpret_cast<unsigned*>(&lo);
    r.y = *reinterpret_cast<unsigned*>(&hi);
    return r;
}

__device__ __forceinline__ void cp16(uint32_t dst, const void* src, uint32_t srcsz) {
    asm volatile("cp.async.cg.shared.global [%0], [%1], 16, %2;"
                 :: "r"(dst), "l"(src), "r"(srcsz) : "memory");
}
__device__ __forceinline__ void cp_commit() {
    asm volatile("cp.async.commit_group;" ::: "memory");
}
template <int N> __device__ __forceinline__ void cp_wait() {
    asm volatile("cp.async.wait_group %0;" :: "n"(N) : "memory");
}

__device__ __forceinline__ void ldsm4(uint32_t* r, uint32_t addr) {
    asm volatile("ldmatrix.sync.aligned.m8n8.x4.shared.b16 {%0,%1,%2,%3}, [%4];"
                 : "=r"(r[0]), "=r"(r[1]), "=r"(r[2]), "=r"(r[3]) : "r"(addr));
}

__device__ __forceinline__ void mma_f16(float* d, const uint32_t* a,
                                        uint32_t b0, uint32_t b1) {
    asm volatile(
        "mma.sync.aligned.m16n8k16.row.col.f32.f16.f16.f32 "
        "{%0,%1,%2,%3}, {%4,%5,%6,%7}, {%8,%9}, {%0,%1,%2,%3};"
        : "+f"(d[0]), "+f"(d[1]), "+f"(d[2]), "+f"(d[3])
        : "r"(a[0]), "r"(a[1]), "r"(a[2]), "r"(a[3]), "r"(b0), "r"(b1));
}

__device__ __forceinline__ void stg_cs2(float* p, float a, float b) {
    asm volatile("st.global.cs.v2.f32 [%0], {%1,%2};"
                 :: "l"(p), "f"(a), "f"(b) : "memory");
}

// ---------------------------------------------------------------------------
// Kernel 1 (prep): blocks [0,1024) L2-normalize one x-row each into g_xnh and
// zero g_rowsum (block 0 also zeroes g_loss and sniffs label dtype);
// blocks [1024, 1024+CONVBLK) convert W f32 -> fp16 (8 elems/thread, __ldcs).
// ---------------------------------------------------------------------------
__global__ void prep_kernel(const float* __restrict__ x,
                            const float* __restrict__ W,
                            const int* __restrict__ labels_raw) {
    int t = threadIdx.x;            // 256 threads
    if (blockIdx.x < MROWS) {
        int row = blockIdx.x;
        float s = 0.0f;
        float4 v = make_float4(0.f, 0.f, 0.f, 0.f);
        if (t < 128) {
            v = ((const float4*)(x + (size_t)row * KDIM))[t];
            s = v.x * v.x + v.y * v.y + v.z * v.z + v.w * v.w;
        }
        #pragma unroll
        for (int o = 16; o > 0; o >>= 1) s += __shfl_xor_sync(0xffffffffu, s, o);
        __shared__ float ws[8];
        int lane = t & 31, wid = t >> 5;
        if (lane == 0) ws[wid] = s;
        __syncthreads();
        float tot = ws[0] + ws[1] + ws[2] + ws[3];
        float inv = 1.0f / fmaxf(sqrtf(tot), 1e-12f);
        if (t < 128) {
            float4 o4 = make_float4(v.x * inv, v.y * inv, v.z * inv, v.w * inv);
            ((uint2*)(g_xnh + (size_t)row * KDIM))[t] = f4toh4(o4);
        }
        if (t == 0) g_rowsum[row] = 0.0f;

        if (row == 0) {
            // label dtype sniff on words [0,1024): all odd words zero => int64
            __shared__ int nz;
            if (t == 0) { nz = 0; g_loss = 0.0f; }
            __syncthreads();
            int a = labels_raw[4 * t + 1] | labels_raw[4 * t + 3];
            if (a != 0) atomicAdd(&nz, 1);
            __syncthreads();
            if (t == 0) g_isI64 = (nz == 0);
        }
    } else {
        size_t i8 = (size_t)(blockIdx.x - MROWS) * 256 + t;
        if (i8 >= NCHUNK8) return;
        float4 a = __ldcs(((const float4*)W) + i8 * 2);
        float4 b = __ldcs(((const float4*)W) + i8 * 2 + 1);
        uint2 lo = f4toh4(a), hi = f4toh4(b);
        ((uint4*)g_wh)[i8] = make_uint4(lo.x, lo.y, hi.x, hi.y);
    }
}

// ---------------------------------------------------------------------------
// Kernel 2: wf = xn @ W^T, fp16 m16n8k16 mma.sync + ldmatrix, cp.async
// 3-stage pipeline, occupancy 2, fused per-row exp sums via atomics.
// wf stores use st.global.cs (streaming) to keep W fp16 resident in L2.
// ---------------------------------------------------------------------------
__global__ __launch_bounds__(256, 2)
void gemm_f16(float* __restrict__ wf) {
    extern __shared__ char smem[];

    const int tid   = threadIdx.x;
    const int lane  = tid & 31;
    const int wid   = tid >> 5;
    const int warpM = wid & 1;     // 2 warps in M (64 rows each)
    const int warpN = wid >> 1;    // 4 warps in N (32 cols each)
    const int g     = lane >> 2;
    const int t     = lane & 3;
    const int rowBase = blockIdx.x * BM;
    const int colBase = blockIdx.y * BN;

    const uint32_t sbase = smem_u32(smem);

    float acc[4][4][4];
    #pragma unroll
    for (int mi = 0; mi < 4; ++mi)
        #pragma unroll
        for (int ni = 0; ni < 4; ++ni)
            #pragma unroll
            for (int r = 0; r < 4; ++r) acc[mi][ni][r] = 0.0f;

    // cp.async mapping: 1024 16B-chunks per operand tile, 4 per thread
    const int cS = tid & 7;
    uint32_t dA[4], dB[4];
    const __half* gA[4];
    const __half* gB[4];
    uint32_t bSz[4];
    #pragma unroll
    for (int i = 0; i < 4; ++i) {
        int s = i * 256 + tid, r = s >> 3;
        dA[i] = swz(r, cS);
        dB[i] = AST + swz(r, cS);
        gA[i] = g_xnh + (size_t)(rowBase + r) * KDIM + cS * 8;
        int n = colBase + r;
        bool ok = n < CCLS;
        gB[i] = g_wh + (ok ? (size_t)n * KDIM + cS * 8 : 0);
        bSz[i] = ok ? 16u : 0u;
    }

    auto cp_stage = [&](int slot, int ko) {
        uint32_t base = sbase + slot * STAGE_BYTES;
        #pragma unroll
        for (int i = 0; i < 4; ++i) cp16(base + dA[i], gA[i] + ko, 16);
        #pragma unroll
        for (int i = 0; i < 4; ++i) cp16(base + dB[i], gB[i] + ko, bSz[i]);
    };

    // ldmatrix per-lane addressing
    const int rIn  = lane & 15;
    const int kHal = lane >> 4;

    auto compute = [&](int slot) {
        const uint32_t aBase = sbase + slot * STAGE_BYTES;
        const uint32_t bBase = aBase + AST;
        #pragma unroll
        for (int ks = 0; ks < 4; ++ks) {
            const int c16 = ks * 2 + kHal;
            uint32_t af[4][4], bf[2][4];
            #pragma unroll
            for (int mi = 0; mi < 4; ++mi)
                ldsm4(af[mi], aBase + swz(warpM * 64 + mi * 16 + rIn, c16));
            #pragma unroll
            for (int nb = 0; nb < 2; ++nb)
                ldsm4(bf[nb], bBase + swz(warpN * 32 + nb * 16 + rIn, c16));
            #pragma unroll
            for (int mi = 0; mi < 4; ++mi)
                #pragma unroll
                for (int ni = 0; ni < 4; ++ni)
                    mma_f16(acc[mi][ni], af[mi],
                            bf[ni >> 1][ni & 1], bf[ni >> 1][(ni & 1) + 2]);
        }
    };

    // prologue: fill stages 0,1
    cp_stage(0, 0);  cp_commit();
    cp_stage(1, BK); cp_commit();

    #pragma unroll 1
    for (int kb = 0; kb < KSTAGES; ++kb) {
        cp_wait<1>();          // stage kb arrived
        __syncthreads();       // visible to all warps; prior compute done
        if (kb + 2 < KSTAGES) cp_stage((kb + 2) % NSTAGE, (kb + 2) * BK);
        cp_commit();           // keep group counting uniform
        compute(kb % NSTAGE);
    }

    // epilogue: streaming float2 stores (nG even & CCLS even -> pair valid) +
    // fused exp rowsums
    #pragma unroll
    for (int mi = 0; mi < 4; ++mi) {
        int mG0 = rowBase + warpM * 64 + mi * 16 + g;
        int mG1 = mG0 + 8;
        float s0 = 0.0f, s1 = 0.0f;
        #pragma unroll
        for (int ni = 0; ni < 4; ++ni) {
            int nG = colBase + warpN * 32 + ni * 8 + 2 * t;
            float c0 = acc[mi][ni][0], c1 = acc[mi][ni][1];
            float c2 = acc[mi][ni][2], c3 = acc[mi][ni][3];
            if (nG < CCLS) {
                stg_cs2(wf + (size_t)mG0 * CCLS + nG, c0, c1);
                stg_cs2(wf + (size_t)mG1 * CCLS + nG, c2, c3);
                s0 += __expf(S_SCALE * c0) + __expf(S_SCALE * c1);
                s1 += __expf(S_SCALE * c2) + __expf(S_SCALE * c3);
            }
        }
        s0 += __shfl_xor_sync(0xffffffffu, s0, 1);
        s0 += __shfl_xor_sync(0xffffffffu, s0, 2);
        s1 += __shfl_xor_sync(0xffffffffu, s1, 1);
        s1 += __shfl_xor_sync(0xffffffffu, s1, 2);
        if (t == 0) {
            atomicAdd(&g_rowsum[mG0], s0);
            atomicAdd(&g_rowsum[mG1], s1);
        }
    }
}

// ---------------------------------------------------------------------------
// Kernel 3: arcface loss partials. 16 blocks x 64 threads (one per sample),
// partial sums atomically into g_loss. Kernel 4 finalizes.
// ---------------------------------------------------------------------------
__global__ void loss_partial(const float* __restrict__ wf,
                             const int* __restrict__ labels_raw) {
    int i = blockIdx.x * 64 + threadIdx.x;   // 0..1023

    int lab;
    if (g_isI64) lab = (int)((const long long*)labels_raw)[i];
    else         lab = labels_raw[i];

    float tgt = wf[(size_t)i * CCLS + lab];
    float tc  = fminf(fmaxf(tgt, -1.0f + EPS_CL), 1.0f - EPS_CL);
    float num = S_SCALE * cosf(acosf(tc) + MARGIN);
    float excl  = g_rowsum[i] - __expf(S_SCALE * tgt);
    float denom = __expf(num) + excl;
    float L = num - logf(denom);

    #pragma unroll
    for (int o = 16; o > 0; o >>= 1) L += __shfl_xor_sync(0xffffffffu, L, o);
    __shared__ float w0;
    if (threadIdx.x == 0) w0 = L;
    __syncthreads();
    if (threadIdx.x == 32 && (threadIdx.x & 31) == 0) atomicAdd(&g_loss, w0 + L);
}

__global__ void loss_final(float* __restrict__ out, int lossIdx) {
    out[lossIdx] = -(g_loss * (1.0f / 1024.0f));
}

// ---------------------------------------------------------------------------
extern "C" void kernel_launch(void* const* d_in, const int* in_sizes, int n_in,
                              void* d_out, int out_size) {
    const float* x      = (const float*)d_in[0];   // [1024, 512] f32
    const float* W      = (const float*)d_in[1];   // [85742, 512] f32
    const int*   labels = (const int*)d_in[2];     // [1024] int32 or int64
    float* out = (float*)d_out;                    // wf [1024*85742] ++ loss

    prep_kernel<<<MROWS + CONVBLK, 256>>>(x, W, labels);

    cudaFuncSetAttribute(gemm_f16, cudaFuncAttributeMaxDynamicSharedMemorySize,
                         NSTAGE * STAGE_BYTES);
    dim3 grid(MROWS / BM, (CCLS + BN - 1) / BN);   // (8, 670), M fast
    gemm_f16<<<grid, 256, NSTAGE * STAGE_BYTES>>>(out);

    loss_partial<<<16, 64>>>(out, labels);
    loss_final<<<1, 1>>>(out, out_size - 1);
}